// round 2
// baseline (speedup 1.0000x reference)
#include <cuda_runtime.h>
#include <cuda_bf16.h>
#include <stdint.h>

// GCNProtein: 6-layer GCN, 1M nodes, 16M edges, dims 1->3->3->3->3->3->1.
// Round 2: build dst-grouped CSR once per call (hist + scan + scatter), then
// pull-mode aggregation: one thread per node sums gathered neighbor messages
// in registers and applies norm/W/bias/ReLU in the same kernel. Zero atomics
// in the 6 layer passes; atomics only in the one-time build.

#define NMAX 1000000
#define EMAX 16000000
#define SCAN_ITEMS 16
#define SCAN_THREADS 256
#define SCAN_BLOCK_ELEMS (SCAN_ITEMS * SCAN_THREADS)   // 4096
#define MAX_SCAN_BLOCKS 256                            // ceil(1e6/4096)=245

__device__ float  g_x1[NMAX];        // scalar messages (layer 1 in, layer 6 in)
__device__ float4 g_x3a[NMAX];       // 3-wide messages, double buffered
__device__ float4 g_x3b[NMAX];
__device__ int    g_cnt[NMAX];       // in-degree counts
__device__ int    g_off[NMAX + 1];   // CSR offsets (by dst)
__device__ int    g_cursor[NMAX];    // scatter cursors
__device__ int    g_perm[EMAX];      // src indices grouped by dst
__device__ int    g_bsum[MAX_SCAN_BLOCKS];
__device__ int    g_bsum2[MAX_SCAN_BLOCKS];

// ---------------- build phase ----------------

// x1 = feat*norm ; cnt = 0
__global__ void k_init(const float* __restrict__ feat, const float* __restrict__ norm, int n) {
    int i = blockIdx.x * blockDim.x + threadIdx.x;
    if (i < n) {
        g_x1[i] = feat[i] * norm[i];
        g_cnt[i] = 0;
    }
}

__global__ void k_hist(const int* __restrict__ dst, int E) {
    int e = blockIdx.x * blockDim.x + threadIdx.x;
    if (e < E) atomicAdd(&g_cnt[dst[e]], 1);   // no return value used -> REDG
}

// per-block exclusive scan of g_cnt into g_off (partial), block totals to g_bsum
__global__ void k_scanA(int n) {
    int tid = threadIdx.x;
    int base = blockIdx.x * SCAN_BLOCK_ELEMS + tid * SCAN_ITEMS;
    int loc[SCAN_ITEMS];
    int s = 0;
#pragma unroll
    for (int k = 0; k < SCAN_ITEMS; k++) {
        int idx = base + k;
        int v = (idx < n) ? g_cnt[idx] : 0;
        loc[k] = s; s += v;
    }
    int lane = tid & 31, wid = tid >> 5;
    int x = s;
#pragma unroll
    for (int o = 1; o < 32; o <<= 1) {
        int y = __shfl_up_sync(0xFFFFFFFFu, x, o);
        if (lane >= o) x += y;
    }
    __shared__ int wsum[8];
    if (lane == 31) wsum[wid] = x;
    __syncthreads();
    int woff = 0;
    for (int w = 0; w < wid; w++) woff += wsum[w];
    int excl = woff + x - s;   // exclusive prefix of this thread's chunk
#pragma unroll
    for (int k = 0; k < SCAN_ITEMS; k++) {
        int idx = base + k;
        if (idx < n) g_off[idx] = excl + loc[k];
    }
    if (tid == SCAN_THREADS - 1) g_bsum[blockIdx.x] = woff + x;
}

// one block: exclusive scan of block sums
__global__ void k_scanB(int nb) {
    int tid = threadIdx.x;
    int v = (tid < nb) ? g_bsum[tid] : 0;
    int lane = tid & 31, wid = tid >> 5;
    int x = v;
#pragma unroll
    for (int o = 1; o < 32; o <<= 1) {
        int y = __shfl_up_sync(0xFFFFFFFFu, x, o);
        if (lane >= o) x += y;
    }
    __shared__ int wsum[8];
    if (lane == 31) wsum[wid] = x;
    __syncthreads();
    int woff = 0;
    for (int w = 0; w < wid; w++) woff += wsum[w];
    if (tid < nb) g_bsum2[tid] = woff + x - v;
}

// add block offsets -> final g_off, copy to g_cursor, set sentinel
__global__ void k_scanC(int n, int E) {
    int i = blockIdx.x * blockDim.x + threadIdx.x;
    if (i < n) {
        int o = g_off[i] + g_bsum2[i / SCAN_BLOCK_ELEMS];
        g_off[i] = o;
        g_cursor[i] = o;
    }
    if (i == 0) g_off[n] = E;
}

// place src of each edge into its dst's segment
__global__ void k_scatter(const int* __restrict__ src, const int* __restrict__ dst, int E) {
    int e = blockIdx.x * blockDim.x + threadIdx.x;
    if (e >= E) return;
    int d = dst[e];
    int pos = atomicAdd(&g_cursor[d], 1);
    g_perm[pos] = src[e];
}

// ---------------- layer kernels (pull-mode, fused transform) ----------------

__device__ __forceinline__ float gather_sum_s(const float* __restrict__ xin, int beg, int end) {
    float a = 0.f;
    int j = beg;
    for (; j + 4 <= end; j += 4) {
        int s0 = g_perm[j], s1 = g_perm[j + 1], s2 = g_perm[j + 2], s3 = g_perm[j + 3];
        a += xin[s0] + xin[s1] + xin[s2] + xin[s3];
    }
    for (; j < end; j++) a += xin[g_perm[j]];
    return a;
}

__device__ __forceinline__ void gather_sum_v(const float4* __restrict__ xin, int beg, int end,
                                             float& a0, float& a1, float& a2) {
    a0 = 0.f; a1 = 0.f; a2 = 0.f;
    int j = beg;
    for (; j + 4 <= end; j += 4) {
        int s0 = g_perm[j], s1 = g_perm[j + 1], s2 = g_perm[j + 2], s3 = g_perm[j + 3];
        float4 v0 = xin[s0], v1 = xin[s1], v2 = xin[s2], v3 = xin[s3];
        a0 += v0.x + v1.x + v2.x + v3.x;
        a1 += v0.y + v1.y + v2.y + v3.y;
        a2 += v0.z + v1.z + v2.z + v3.z;
    }
    for (; j < end; j++) {
        float4 v = xin[g_perm[j]];
        a0 += v.x; a1 += v.y; a2 += v.z;
    }
}

// L1: scalar in -> 3-wide out.  t = agg*nm; h=relu(t*W1+b1); xout = h*nm
__global__ void k_layer1(const float* __restrict__ norm,
                         const float* __restrict__ W, const float* __restrict__ b,
                         float4* __restrict__ xout, int n) {
    int i = blockIdx.x * blockDim.x + threadIdx.x;
    if (i >= n) return;
    int beg = g_off[i], end = g_off[i + 1];
    float t = gather_sum_s(g_x1, beg, end);
    float nm = norm[i];
    t *= nm;
    float h0 = fmaxf(fmaf(t, W[0], b[0]), 0.f);
    float h1 = fmaxf(fmaf(t, W[1], b[1]), 0.f);
    float h2 = fmaxf(fmaf(t, W[2], b[2]), 0.f);
    xout[i] = make_float4(h0 * nm, h1 * nm, h2 * nm, 0.f);
}

// L2..L4: 3-wide -> 3-wide, W is 3x3 row-major
__global__ void k_layer3(const float4* __restrict__ xin, float4* __restrict__ xout,
                         const float* __restrict__ norm,
                         const float* __restrict__ W, const float* __restrict__ b, int n) {
    int i = blockIdx.x * blockDim.x + threadIdx.x;
    if (i >= n) return;
    int beg = g_off[i], end = g_off[i + 1];
    float a0, a1, a2;
    gather_sum_v(xin, beg, end, a0, a1, a2);
    float nm = norm[i];
    a0 *= nm; a1 *= nm; a2 *= nm;
    float h0 = fmaxf(fmaf(a0, W[0], fmaf(a1, W[3], fmaf(a2, W[6], b[0]))), 0.f);
    float h1 = fmaxf(fmaf(a0, W[1], fmaf(a1, W[4], fmaf(a2, W[7], b[1]))), 0.f);
    float h2 = fmaxf(fmaf(a0, W[2], fmaf(a1, W[5], fmaf(a2, W[8], b[2]))), 0.f);
    xout[i] = make_float4(h0 * nm, h1 * nm, h2 * nm, 0.f);
}

// L5: 3-wide -> scalar out via folded W6:  x1 = nm * (relu((agg*nm)@W5+b5) @ W6)
__global__ void k_layer5(const float4* __restrict__ xin,
                         const float* __restrict__ norm,
                         const float* __restrict__ W5, const float* __restrict__ b5,
                         const float* __restrict__ W6, int n) {
    int i = blockIdx.x * blockDim.x + threadIdx.x;
    if (i >= n) return;
    int beg = g_off[i], end = g_off[i + 1];
    float a0, a1, a2;
    gather_sum_v(xin, beg, end, a0, a1, a2);
    float nm = norm[i];
    a0 *= nm; a1 *= nm; a2 *= nm;
    float h0 = fmaxf(fmaf(a0, W5[0], fmaf(a1, W5[3], fmaf(a2, W5[6], b5[0]))), 0.f);
    float h1 = fmaxf(fmaf(a0, W5[1], fmaf(a1, W5[4], fmaf(a2, W5[7], b5[1]))), 0.f);
    float h2 = fmaxf(fmaf(a0, W5[2], fmaf(a1, W5[5], fmaf(a2, W5[8], b5[2]))), 0.f);
    g_x1[i] = nm * (h0 * W6[0] + h1 * W6[1] + h2 * W6[2]);
}

// L6: scalar -> output.  out = relu(nm*agg + b6)
__global__ void k_layer6(const float* __restrict__ norm,
                         const float* __restrict__ b6,
                         float* __restrict__ out, int n) {
    int i = blockIdx.x * blockDim.x + threadIdx.x;
    if (i >= n) return;
    int beg = g_off[i], end = g_off[i + 1];
    float t = gather_sum_s(g_x1, beg, end);
    out[i] = fmaxf(fmaf(norm[i], t, b6[0]), 0.f);
}

// ---------------- launch ----------------

extern "C" void kernel_launch(void* const* d_in, const int* in_sizes, int n_in,
                              void* d_out, int out_size) {
    const int* big_i[2] = {nullptr, nullptr};
    const float* big_f[2] = {nullptr, nullptr};
    const float* small[12] = {nullptr};
    int ni = 0, nf = 0, ns = 0;
    int N = 0, E = 0;
    for (int i = 0; i < n_in; i++) {
        int sz = in_sizes[i];
        if (sz >= 10000000) {
            if (ni < 2) { big_i[ni++] = (const int*)d_in[i]; E = sz; }
        } else if (sz >= 100000) {
            if (nf < 2) { big_f[nf++] = (const float*)d_in[i]; N = sz; }
        } else {
            if (ns < 12) small[ns++] = (const float*)d_in[i];
        }
    }
    const float* feat = big_f[0];
    const float* norm = big_f[1];
    const int* src = big_i[0];
    const int* dst = big_i[1];
    const float *W1 = small[0], *b1 = small[1];
    const float *W2 = small[2], *b2 = small[3];
    const float *W3 = small[4], *b3 = small[5];
    const float *W4 = small[6], *b4 = small[7];
    const float *W5 = small[8], *b5 = small[9];
    const float *W6 = small[10], *b6 = small[11];
    float* out = (float*)d_out;

    const int TB = 256;
    int gn = (N + TB - 1) / TB;
    int ge = (E + TB - 1) / TB;
    int nscan = (N + SCAN_BLOCK_ELEMS - 1) / SCAN_BLOCK_ELEMS;

    // build CSR (grouped by dst)
    k_init<<<gn, TB>>>(feat, norm, N);
    k_hist<<<ge, TB>>>(dst, E);
    k_scanA<<<nscan, SCAN_THREADS>>>(N);
    k_scanB<<<1, SCAN_THREADS>>>(nscan);
    k_scanC<<<gn, TB>>>(N, E);
    k_scatter<<<ge, TB>>>(src, dst, E);

    // 6 fused layers, zero atomics
    k_layer1<<<gn, TB>>>(norm, W1, b1, g_x3a, N);
    k_layer3<<<gn, TB>>>(g_x3a, g_x3b, norm, W2, b2, N);
    k_layer3<<<gn, TB>>>(g_x3b, g_x3a, norm, W3, b3, N);
    k_layer3<<<gn, TB>>>(g_x3a, g_x3b, norm, W4, b4, N);
    k_layer5<<<gn, TB>>>(g_x3b, norm, W5, b5, W6, N);
    k_layer6<<<gn, TB>>>(norm, b6, out, N);
}